// round 13
// baseline (speedup 1.0000x reference)
#include <cuda_runtime.h>
#include <math.h>
#include <stdint.h>

#define CIN   16
#define OC    64
#define NPIX  7200          // 8*30*30
#define KDIM  144
#define ASTR  148           // A row stride (u32) -> conflict-free MMA fragment LDS
#define MT    64            // M rows per block
#define NBLK  113           // ceil(7200/64)
#define BFRAG (18*9*64)     // 10368 u32 fragment-major B (incl. ones/pad tile)

// Precomputed (no allocation allowed)
__device__ uint32_t g_wfrag[BFRAG];
__device__ float    g_koff[OC];

// main-kernel smem layout (bytes)
#define KOFF_OFF 0
#define XSUM_OFF 256
#define SDW_OFF  512
#define A_OFF    1024
#define B_OFF    (A_OFF + MT*ASTR*4)        // 1024+37888 = 38912
#define SMEM_BYTES (B_OFF + BFRAG*4)        // +41472 = 80384

__device__ __forceinline__ uint32_t f2tf(float f) {
    uint32_t u;
    asm("cvt.rna.tf32.f32 %0, %1;" : "=r"(u) : "f"(f));
    return u;
}

__device__ __forceinline__ void mma_tf32(float* d, const uint32_t* a, const uint32_t* b) {
    asm volatile(
        "mma.sync.aligned.m16n8k8.row.col.f32.tf32.tf32.f32 "
        "{%0,%1,%2,%3}, {%4,%5,%6,%7}, {%8,%9}, {%0,%1,%2,%3};"
        : "+f"(d[0]), "+f"(d[1]), "+f"(d[2]), "+f"(d[3])
        : "r"(a[0]), "r"(a[1]), "r"(a[2]), "r"(a[3]), "r"(b[0]), "r"(b[1]));
}

// ---------------- prep: fragment-major exp(k+5) + koff ----------------
__global__ __launch_bounds__(256)
void prep_kernel(const float* __restrict__ kw_,
                 const float* __restrict__ bias,
                 const float* __restrict__ dxp) {
    const int b = blockIdx.x;
    const int t = threadIdx.x;
    if (b < 36) {
        const int i  = b * 256 + t;        // == kf*64 + n (natural order)
        const int kf = i >> 6, n = i & 63;
        const int idx = ((kf >> 3) * 9 + (n >> 3)) * 64
                      + ((n & 7) * 4 + (kf & 3)) * 2 + ((kf >> 2) & 1);
        g_wfrag[idx] = f2tf(expf(kw_[i] + 5.0f));
    } else {
        // ones/pad tile (nt = 8)
        for (int i = t; i < 18 * 64; i += 256) {
            const int ks = i >> 6, e = i & 63;
            g_wfrag[(ks * 9 + 8) * 64 + e] = (e < 8) ? 0x3f800000u : 0u;
        }
        // koff reduction: 4 threads per n
        __shared__ float part[256];
        const int n = t & 63, q = t >> 6;
        float s = 0.0f;
        #pragma unroll 4
        for (int j = 0; j < 36; j++)
            s += kw_[(q * 36 + j) * OC + n];
        part[t] = s;
        __syncthreads();
        if (t < OC)
            g_koff[t] = bias[t]
                      - dxp[0] * (part[t] + part[t + 64] + part[t + 128] + part[t + 192]);
    }
}

template<int NT0, int NTN>
__device__ __forceinline__ void mma_loop(float (&acc)[3][4],
                                         const uint32_t* __restrict__ Arow,
                                         const uint32_t* __restrict__ smB,
                                         int lane) {
    #pragma unroll
    for (int ks = 0; ks < 18; ks++) {
        uint32_t a[4];
        a[0] = Arow[ks * 8];
        a[1] = Arow[ks * 8 + 8 * ASTR];
        a[2] = Arow[ks * 8 + 4];
        a[3] = Arow[ks * 8 + 4 + 8 * ASTR];
        #pragma unroll
        for (int j = 0; j < NTN; j++) {
            const uint2 bv = *(const uint2*)(smB + (ks * 9 + NT0 + j) * 64 + lane * 2);
            uint32_t b[2] = {bv.x, bv.y};
            mma_tf32(acc[j], a, b);
        }
    }
}

__global__ __launch_bounds__(512, 1)
void conv_mma_kernel(const float* __restrict__ x,
                     const float* __restrict__ dwp,
                     float* __restrict__ out) {
    extern __shared__ char sm[];
    float*    koff_s = (float*)(sm + KOFF_OFF);
    float*    xsum_s = (float*)(sm + XSUM_OFF);
    float*    sdw_s  = (float*)(sm + SDW_OFF);
    uint32_t* smA    = (uint32_t*)(sm + A_OFF);
    uint32_t* smB    = (uint32_t*)(sm + B_OFF);

    const int t    = threadIdx.x;
    const int lane = t & 31;
    const int wid  = t >> 5;

    // ---- Copy pre-staged B fragments global -> smem (vectorized, L2-broadcast) ----
    {
        const uint4* src = (const uint4*)g_wfrag;
        uint4* dst = (uint4*)smB;
        #pragma unroll
        for (int i = t; i < BFRAG / 4; i += 512)   // 2592 uint4
            dst[i] = src[i];
    }
    if (t < OC) koff_s[t] = g_koff[t];
    if (t == 0) sdw_s[0] = dwp[0];

    // ---- Stage A: im2col tf32(clamp(x+5)); thread = (row, c-octet); immediate offsets ----
    {
        const int m = t >> 3;          // 0..63
        const int s = t & 7;           // c and c+8
        const int p = blockIdx.x * MT + m;
        uint32_t* ar0 = smA + m * ASTR + s;
        uint32_t* ar1 = ar0 + 8;
        if (p < NPIX) {
            const int img = p / 900, rem = p % 900, i = rem / 30, jj = rem % 30;
            const float* xb0 = x + (size_t)img * 16384 + s * 1024 + i * 32 + jj;
            const float* xb1 = xb0 + 8 * 1024;
            #pragma unroll
            for (int pos = 0; pos < 9; pos++) {
                const int go = (pos / 3) * 32 + (pos % 3);   // compile-time
                ar0[pos * 16] = f2tf(fmaxf(xb0[go] + 5.0f, 1e-12f));
                ar1[pos * 16] = f2tf(fmaxf(xb1[go] + 5.0f, 1e-12f));
            }
        } else {
            #pragma unroll
            for (int pos = 0; pos < 9; pos++) {
                ar0[pos * 16] = 0u;
                ar1[pos * 16] = 0u;
            }
        }
    }
    __syncthreads();

    // ---- MMA: warp = (m-tile wm, n-group wn); groups {0-2},{3-4},{5-6},{7-8} ----
    const int wm  = wid & 3;
    const int wn  = wid >> 2;
    const int gr  = lane >> 2;
    const int tig = lane & 3;

    float acc[3][4];
    #pragma unroll
    for (int j = 0; j < 3; j++)
        #pragma unroll
        for (int q = 0; q < 4; q++) acc[j][q] = 0.0f;

    const uint32_t* Arow = smA + (wm * 16 + gr) * ASTR + tig;
    if      (wn == 0) mma_loop<0, 3>(acc, Arow, smB, lane);
    else if (wn == 1) mma_loop<3, 2>(acc, Arow, smB, lane);
    else if (wn == 2) mma_loop<5, 2>(acc, Arow, smB, lane);
    else              mma_loop<7, 2>(acc, Arow, smB, lane);

    // ---- xsum from ones column (tile 8 = group 3 j=1, local col 0) ----
    if (wn == 3 && tig == 0) {
        xsum_s[wm * 16 + gr]     = acc[1][0];
        xsum_s[wm * 16 + gr + 8] = acc[1][2];
    }
    __syncthreads();

    // ---- Epilogue ----
    const int NTout  = (wn == 0) ? 3 : ((wn == 3) ? 1 : 2);
    const int ntbase = (wn == 0) ? 0 : (2 * wn + 1);
    const int r1 = wm * 16 + gr;
    const int p1 = blockIdx.x * MT + r1;
    const float sdw = sdw_s[0];
    #pragma unroll
    for (int h = 0; h < 2; h++) {
        const int p = p1 + h * 8;
        if (p < NPIX) {
            const int img = p / 900, rem = p % 900, i = rem / 30, jj = rem % 30;
            const float corr = sdw * (xsum_s[r1 + h * 8] - 720.0f);
            float* ob = out + (size_t)img * OC * 900 + i * 30 + jj;
            for (int j = 0; j < NTout; j++) {
                const int cb = (ntbase + j) * 8 + 2 * tig;
                ob[(size_t)cb * 900]       = acc[j][h * 2]     - corr + koff_s[cb];
                ob[(size_t)(cb + 1) * 900] = acc[j][h * 2 + 1] - corr + koff_s[cb + 1];
            }
        }
    }
}

extern "C" void kernel_launch(void* const* d_in, const int* in_sizes, int n_in,
                              void* d_out, int out_size) {
    const float* x    = (const float*)d_in[0];
    const float* k    = (const float*)d_in[1];
    const float* bias = (const float*)d_in[2];
    const float* dx   = (const float*)d_in[3];
    const float* dw   = (const float*)d_in[4];
    float* out = (float*)d_out;

    prep_kernel<<<37, 256>>>(k, bias, dx);
    cudaFuncSetAttribute(conv_mma_kernel,
                         cudaFuncAttributeMaxDynamicSharedMemorySize, SMEM_BYTES);
    conv_mma_kernel<<<NBLK, 512, SMEM_BYTES>>>(x, dw, out);
}